// round 4
// baseline (speedup 1.0000x reference)
#include <cuda_runtime.h>

#define BROWS 4096
#define FIN   2048
#define FBOT  256
#define NCLS  31

// ---------------- scratch (device globals; no allocation) ----------------
__device__ float g_H[2 * BROWS * FBOT];      // relu(bottleneck) for src|tar : 8 MB
__device__ float g_s2[2 * BROWS];            // per-row squared norms
__device__ float g_logp[BROWS];              // per-source-row log prob at label
__device__ float g_colpart[32 * 256];        // column-sum partials (2 dom x 16 chunks x 256)
__device__ float g_part[1024 * 2];           // pairwise block partials (gk1, gk5)

// ================= K1: fused bottleneck GEMM + bias + relu =================
// X[8192,2048] @ Wb[2048,256] ; BM=128 BN=128 BK=16, 256 threads, 8x8/thread
__global__ __launch_bounds__(256) void k_bottleneck(
    const float* __restrict__ src, const float* __restrict__ tgt,
    const float* __restrict__ Wb, const float* __restrict__ bb)
{
    __shared__ float As[128][16];
    __shared__ float Bs[16][132];   // padded

    const int bn = blockIdx.x, bm = blockIdx.y;
    const int row0 = bm * 128;
    const float* A = (row0 < BROWS) ? (src + (size_t)row0 * FIN)
                                    : (tgt + (size_t)(row0 - BROWS) * FIN);
    const int tid = threadIdx.x;
    const int tx = tid & 15, ty = tid >> 4;

    float acc[8][8];
#pragma unroll
    for (int i = 0; i < 8; i++)
#pragma unroll
        for (int j = 0; j < 8; j++) acc[i][j] = 0.f;

    for (int k0 = 0; k0 < FIN; k0 += 16) {
#pragma unroll
        for (int i = 0; i < 2; i++) {                    // A tile 128x16
            int idx = tid + i * 256;
            int r = idx >> 2, c4 = idx & 3;
            float4 v = *(const float4*)(A + (size_t)r * FIN + k0 + c4 * 4);
            *(float4*)&As[r][c4 * 4] = v;
        }
#pragma unroll
        for (int i = 0; i < 2; i++) {                    // B tile 16x128
            int idx = tid + i * 256;
            int r = idx >> 5, c4 = idx & 31;
            float4 v = *(const float4*)(Wb + (size_t)(k0 + r) * FBOT + bn * 128 + c4 * 4);
            *(float4*)&Bs[r][c4 * 4] = v;
        }
        __syncthreads();
#pragma unroll
        for (int k = 0; k < 16; k++) {
            float a[8], b[8];
#pragma unroll
            for (int i = 0; i < 8; i++) a[i] = As[ty * 8 + i][k];
            float4 b0 = *(float4*)&Bs[k][tx * 8];
            float4 b1 = *(float4*)&Bs[k][tx * 8 + 4];
            b[0]=b0.x; b[1]=b0.y; b[2]=b0.z; b[3]=b0.w;
            b[4]=b1.x; b[5]=b1.y; b[6]=b1.z; b[7]=b1.w;
#pragma unroll
            for (int i = 0; i < 8; i++)
#pragma unroll
                for (int j = 0; j < 8; j++) acc[i][j] = fmaf(a[i], b[j], acc[i][j]);
        }
        __syncthreads();
    }
    // epilogue: bias + relu, store H
#pragma unroll
    for (int i = 0; i < 8; i++) {
        int gr = row0 + ty * 8 + i;
        int gc = bn * 128 + tx * 8;
        float4 o0, o1;
#pragma unroll
        for (int j = 0; j < 8; j++) {
            float v = acc[i][j] + bb[gc + j];
            v = fmaxf(v, 0.f);
            if (j < 4) (&o0.x)[j] = v; else (&o1.x)[j - 4] = v;
        }
        *(float4*)&g_H[(size_t)gr * FBOT + gc]     = o0;
        *(float4*)&g_H[(size_t)gr * FBOT + gc + 4] = o1;
    }
}

// ============ K2: classifier logits, softmax margins, CE, row norms ============
// one warp per row; lanes 0..30 = classes, lane 31 accumulates sum(h^2)
__global__ __launch_bounds__(256) void k_classifier(
    const float* __restrict__ Wc, const float* __restrict__ bc,
    const void* __restrict__ labels_raw, float* __restrict__ out)
{
    const int warp = threadIdx.x >> 5, lane = threadIdx.x & 31;
    const int row = blockIdx.x * 8 + warp;
    const float* h = g_H + (size_t)row * FBOT;

    float acc = 0.f;
#pragma unroll 4
    for (int k = 0; k < FBOT; k++) {
        float hv = __ldg(&h[k]);
        float w;
        if (lane < NCLS) w = __ldg(&Wc[k * NCLS + lane]);
        else             w = hv;
        acc = fmaf(hv, w, acc);
    }
    if (lane == 31) g_s2[row] = acc;

    float logit;
    if (lane < NCLS) logit = acc + bc[lane];
    else             logit = -1.0e30f;

    float m = logit;
#pragma unroll
    for (int o = 16; o; o >>= 1) m = fmaxf(m, __shfl_xor_sync(0xffffffffu, m, o));
    float e = (lane < NCLS) ? __expf(logit - m) : 0.f;
    float Z = e;
#pragma unroll
    for (int o = 16; o; o >>= 1) Z += __shfl_xor_sync(0xffffffffu, Z, o);

    int label;
    if (row < BROWS) {
        // autodetect int32 vs int64 labels: int64 labels in [0,31) have all
        // odd 32-bit words == 0 (little-endian). Check the first 16 pairs.
        const int* L32 = (const int*)labels_raw;
        int oddw = (lane < 16) ? __ldg(&L32[2 * lane + 1]) : 0;
        unsigned nz = __ballot_sync(0xffffffffu, oddw != 0);
        if (nz == 0u) label = __ldg(&L32[2 * row]);   // int64 (low word)
        else          label = __ldg(&L32[row]);       // int32
        label = min(max(label, 0), NCLS - 1);
    } else {
        float bv = logit; int bi = lane;
#pragma unroll
        for (int o = 16; o; o >>= 1) {
            float ov = __shfl_xor_sync(0xffffffffu, bv, o);
            int   oi = __shfl_xor_sync(0xffffffffu, bi, o);
            if (ov > bv || (ov == bv && oi < bi)) { bv = ov; bi = oi; }
        }
        label = bi;
    }

    float elab = __shfl_sync(0xffffffffu, e, label);
    float llab = __shfl_sync(0xffffffffu, logit, label);
    float tmp = (lane == label || lane >= NCLS) ? -1.f : e;   // e >= 0
    float me = tmp;
#pragma unroll
    for (int o = 16; o; o >>= 1) me = fmaxf(me, __shfl_xor_sync(0xffffffffu, me, o));
    float margin = (elab - me) / Z;

    if (lane == 0) {
        out[4 + row] = margin;                 // src rows -> [4, 4+B), tar -> [4+B, 4+2B)
        if (row < BROWS) g_logp[row] = llab - m - __logf(Z);
    }
}

// ================= K3: column-sum partials for MMD =================
__global__ __launch_bounds__(256) void k_colsum()
{
    const int chunk = blockIdx.x;   // 0..15
    const int dom   = blockIdx.y;   // 0..1
    const int j     = threadIdx.x;  // 0..255
    const float* Hp = g_H + (size_t)dom * BROWS * FBOT + (size_t)chunk * 256 * FBOT;
    float s = 0.f;
#pragma unroll 4
    for (int i = 0; i < 256; i++) s += Hp[(size_t)i * FBOT + j];
    g_colpart[(dom * 16 + chunk) * 256 + j] = s;
}

// ======== K4: pairwise GEMM (src @ tar^T) + d2 + gaussian kernel sums ========
__global__ __launch_bounds__(256) void k_pairwise()
{
    __shared__ float As[128][16];
    __shared__ float Bs[16][132];
    __shared__ float red[256];

    const float* A  = g_H;                          // src rows
    const float* Bm = g_H + (size_t)BROWS * FBOT;   // tar rows
    const int bn = blockIdx.x, bm = blockIdx.y;
    const int m0 = bm * 128, n0 = bn * 128;
    const int tid = threadIdx.x;
    const int tx = tid & 15, ty = tid >> 4;

    float acc[8][8];
#pragma unroll
    for (int i = 0; i < 8; i++)
#pragma unroll
        for (int j = 0; j < 8; j++) acc[i][j] = 0.f;

    for (int k0 = 0; k0 < FBOT; k0 += 16) {
#pragma unroll
        for (int i = 0; i < 2; i++) {                     // A tile [m][k]
            int idx = tid + i * 256;
            int r = idx >> 2, c4 = idx & 3;
            float4 v = *(const float4*)(A + (size_t)(m0 + r) * FBOT + k0 + c4 * 4);
            *(float4*)&As[r][c4 * 4] = v;
        }
#pragma unroll
        for (int i = 0; i < 2; i++) {                     // B tile, transpose to Bs[k][n]
            int idx = tid + i * 256;
            int r = idx >> 2, c4 = idx & 3;
            float4 v = *(const float4*)(Bm + (size_t)(n0 + r) * FBOT + k0 + c4 * 4);
            Bs[c4 * 4 + 0][r] = v.x; Bs[c4 * 4 + 1][r] = v.y;
            Bs[c4 * 4 + 2][r] = v.z; Bs[c4 * 4 + 3][r] = v.w;
        }
        __syncthreads();
#pragma unroll
        for (int k = 0; k < 16; k++) {
            float a[8], b[8];
#pragma unroll
            for (int i = 0; i < 8; i++) a[i] = As[ty * 8 + i][k];
            float4 b0 = *(float4*)&Bs[k][tx * 8];
            float4 b1 = *(float4*)&Bs[k][tx * 8 + 4];
            b[0]=b0.x; b[1]=b0.y; b[2]=b0.z; b[3]=b0.w;
            b[4]=b1.x; b[5]=b1.y; b[6]=b1.z; b[7]=b1.w;
#pragma unroll
            for (int i = 0; i < 8; i++)
#pragma unroll
                for (int j = 0; j < 8; j++) acc[i][j] = fmaf(a[i], b[j], acc[i][j]);
        }
        __syncthreads();
    }

    // epilogue: d2 = max(s2 + t2 - 2*dot, 0); gk5 = exp(-d2/50); gk1 = gk5^25
    float s2m[8], t2n[8];
#pragma unroll
    for (int i = 0; i < 8; i++) s2m[i] = g_s2[m0 + ty * 8 + i];
#pragma unroll
    for (int j = 0; j < 8; j++) t2n[j] = g_s2[BROWS + n0 + tx * 8 + j];

    float se1 = 0.f, se5 = 0.f;
#pragma unroll
    for (int i = 0; i < 8; i++)
#pragma unroll
        for (int j = 0; j < 8; j++) {
            float d2 = fmaxf(s2m[i] + t2n[j] - 2.f * acc[i][j], 0.f);
            float e5 = __expf(-0.02f * d2);          // exp(-d2/50): 1 MUFU
            float e2 = e5 * e5, e4 = e2 * e2, e8 = e4 * e4, e16 = e8 * e8;
            float e1 = e16 * e8 * e5;                // ^25 = exp(-0.5*d2)
            se5 += e5; se1 += e1;
        }

    const int bidx = bm * gridDim.x + bn;
    red[tid] = se1; __syncthreads();
#pragma unroll
    for (int o = 128; o; o >>= 1) { if (tid < o) red[tid] += red[tid + o]; __syncthreads(); }
    if (tid == 0) g_part[2 * bidx + 0] = red[0];
    __syncthreads();
    red[tid] = se5; __syncthreads();
#pragma unroll
    for (int o = 128; o; o >>= 1) { if (tid < o) red[tid] += red[tid + o]; __syncthreads(); }
    if (tid == 0) g_part[2 * bidx + 1] = red[0];
}

// ================= K5: final deterministic reductions =================
__global__ __launch_bounds__(256) void k_final(float* __restrict__ out)
{
    __shared__ float red[256];
    const int t = threadIdx.x;

    // clf loss
    float s = 0.f;
    for (int i = t; i < BROWS; i += 256) s += g_logp[i];
    red[t] = s; __syncthreads();
#pragma unroll
    for (int o = 128; o; o >>= 1) { if (t < o) red[t] += red[t + o]; __syncthreads(); }
    float clf = -red[0] * (1.0f / BROWS);
    __syncthreads();

    // mmd
    float cs = 0.f, ct = 0.f;
#pragma unroll
    for (int c = 0; c < 16; c++) {
        cs += g_colpart[c * 256 + t];
        ct += g_colpart[(16 + c) * 256 + t];
    }
    float d = (cs - ct) * (1.0f / BROWS);
    red[t] = d * d; __syncthreads();
#pragma unroll
    for (int o = 128; o; o >>= 1) { if (t < o) red[t] += red[t + o]; __syncthreads(); }
    float mmd = red[0];
    __syncthreads();

    // gaussian kernel means
    float s1 = 0.f, s5 = 0.f;
    for (int b = t; b < 1024; b += 256) { s1 += g_part[2 * b]; s5 += g_part[2 * b + 1]; }
    red[t] = s1; __syncthreads();
#pragma unroll
    for (int o = 128; o; o >>= 1) { if (t < o) red[t] += red[t + o]; __syncthreads(); }
    float gk1 = red[0] * (1.0f / 16777216.0f);
    __syncthreads();
    red[t] = s5; __syncthreads();
#pragma unroll
    for (int o = 128; o; o >>= 1) { if (t < o) red[t] += red[t + o]; __syncthreads(); }
    float gk5 = red[0] * (1.0f / 16777216.0f);

    if (t == 0) {
        out[0] = clf;
        out[1] = mmd;
        out[2] = gk1;
        out[3] = gk5;
    }
}

// ============================ launch ============================
extern "C" void kernel_launch(void* const* d_in, const int* in_sizes, int n_in,
                              void* d_out, int out_size)
{
    // Resolve inputs by element count (robust to metadata ordering):
    // source/target: 4096*2048 = 8388608 (order preserved among equals)
    // W_b: 2048*256 = 524288, b_b: 256, W_c: 256*31 = 7936, b_c: 31, labels: 4096
    const float *src = 0, *tgt = 0, *Wb = 0, *bb = 0, *Wc = 0, *bc = 0;
    const void  *lab = 0;
    for (int i = 0; i < n_in; i++) {
        switch (in_sizes[i]) {
            case 8388608: if (!src) src = (const float*)d_in[i];
                          else      tgt = (const float*)d_in[i];
                          break;
            case 524288:  Wb = (const float*)d_in[i]; break;
            case 256:     bb = (const float*)d_in[i]; break;
            case 7936:    Wc = (const float*)d_in[i]; break;
            case 31:      bc = (const float*)d_in[i]; break;
            case 4096:    lab = d_in[i]; break;
            default: break;
        }
    }
    float* out = (float*)d_out;

    dim3 g1(2, 64);
    k_bottleneck<<<g1, 256>>>(src, tgt, Wb, bb);
    k_classifier<<<1024, 256>>>(Wc, bc, lab, out);
    k_colsum<<<dim3(16, 2), 256>>>();
    dim3 g4(32, 32);
    k_pairwise<<<g4, 256>>>();
    k_final<<<1, 256>>>(out);
}